// round 15
// baseline (speedup 1.0000x reference)
#include <cuda_runtime.h>
#include <cuda_bf16.h>
#include <cuda_fp16.h>
#include <cstdint>

#define NN 50000
#define EE 600000

// ---------------- scratch ----------------
__device__ int    g_deg[NN];
__device__ int    g_off[NN + 1];
__device__ int    g_cur[NN];
__device__ int    g_csr[EE];
__device__ __half g_p1[(size_t)NN * 128];   // gathered -> fp16
__device__ float  g_q1[(size_t)NN * 128];
__device__ float  g_h [(size_t)NN * 128];
__device__ __half g_p2[(size_t)NN * 64];    // gathered -> fp16
__device__ float  g_q2[(size_t)NN * 64];
// prepped bf16 hi/lo W images in GEMM smem layout [n][LDK=136], hi then lo
__device__ __align__(16) __nv_bfloat16 g_img1[2 * 256 * 136];
__device__ __align__(16) __nv_bfloat16 g_img2[2 * 128 * 136];

// ---------------- inline dtype detection ----------------
__device__ __forceinline__ int detect_is32(const void* ei, int N) {
    const long long* p = (const long long*)ei;
    int lane = threadIdx.x & 31;
    bool bad = false;
#pragma unroll
    for (int j = 0; j < 2; j++) {
        long long v = p[lane * 2 + j];
        bad |= (v < 0 || v >= (long long)N);
    }
    return __any_sync(0xFFFFFFFF, bad);
}
__device__ __forceinline__ int load_idx(const void* ei, int pos, int is32) {
    if (is32) return ((const int*)ei)[pos];
    return (int)((const long long*)ei)[pos];
}

// ---------------- bf16 split helper ----------------
__device__ __forceinline__ void split_bf16(float v, __nv_bfloat16& hi, __nv_bfloat16& lo) {
    hi = __float2bfloat16(v);
    lo = __float2bfloat16(v - __bfloat162float(hi));
}

// ---------------- setup: zero deg + prep W split-images (fused) ----------------
__global__ void setup_kernel(const float* __restrict__ w1l, const float* __restrict__ w1r,
                             const float* __restrict__ w2l, const float* __restrict__ w2r,
                             __nv_bfloat16* __restrict__ img1,
                             __nv_bfloat16* __restrict__ img2,
                             int* __restrict__ deg, int N) {
    int i = blockIdx.x * blockDim.x + threadIdx.x;
    if (i < N) deg[i] = 0;
    if (i < 32768) {                         // layer 1: NT=256
        int n = i >> 7, k = i & 127;
        float v = (n < 128) ? w1l[k * 128 + n] : w1r[k * 128 + (n - 128)];
        __nv_bfloat16 hi, lo;
        split_bf16(v, hi, lo);
        img1[n * 136 + k] = hi;
        img1[256 * 136 + n * 136 + k] = lo;
    } else if (i < 49152) {                  // layer 2: NT=128
        int j = i - 32768;
        int n = j >> 7, k = j & 127;
        float v = (n < 64) ? w2l[k * 64 + n] : w2r[k * 64 + (n - 64)];
        __nv_bfloat16 hi, lo;
        split_bf16(v, hi, lo);
        img2[n * 136 + k] = hi;
        img2[128 * 136 + n * 136 + k] = lo;
    }
}

// ---------------- CSR build (4 edges per thread, vector loads) ----------------
__device__ __forceinline__ void load_dst4(const void* ei, int E, int i4, int is32,
                                          int d[4], int valid) {
    if (is32) {
        if (valid == 4) {
            int4 v = *(const int4*)((const int*)ei + E + i4);
            d[0] = v.x; d[1] = v.y; d[2] = v.z; d[3] = v.w;
        } else {
            for (int j = 0; j < 4; j++)
                d[j] = (j < valid) ? ((const int*)ei)[E + i4 + j] : -1;
        }
    } else {
        if (valid == 4) {
            longlong2 a = *(const longlong2*)((const long long*)ei + E + i4);
            longlong2 b = *(const longlong2*)((const long long*)ei + E + i4 + 2);
            d[0] = (int)a.x; d[1] = (int)a.y; d[2] = (int)b.x; d[3] = (int)b.y;
        } else {
            for (int j = 0; j < 4; j++)
                d[j] = (j < valid) ? (int)((const long long*)ei)[E + i4 + j] : -1;
        }
    }
}
__device__ __forceinline__ void load_src4(const void* ei, int i4, int is32,
                                          int s[4], int valid) {
    if (is32) {
        if (valid == 4) {
            int4 v = *(const int4*)((const int*)ei + i4);
            s[0] = v.x; s[1] = v.y; s[2] = v.z; s[3] = v.w;
        } else {
            for (int j = 0; j < 4; j++)
                s[j] = (j < valid) ? ((const int*)ei)[i4 + j] : -1;
        }
    } else {
        if (valid == 4) {
            longlong2 a = *(const longlong2*)((const long long*)ei + i4);
            longlong2 b = *(const longlong2*)((const long long*)ei + i4 + 2);
            s[0] = (int)a.x; s[1] = (int)a.y; s[2] = (int)b.x; s[3] = (int)b.y;
        } else {
            for (int j = 0; j < 4; j++)
                s[j] = (j < valid) ? (int)((const long long*)ei)[i4 + j] : -1;
        }
    }
}

__global__ void hist_kernel(const void* __restrict__ ei, int E, int N,
                            int* __restrict__ deg) {
    int is32 = detect_is32(ei, N);
    int i4 = (blockIdx.x * blockDim.x + threadIdx.x) * 4;
    if (i4 >= E) return;
    int valid = E - i4; if (valid > 4) valid = 4;
    int d[4];
    load_dst4(ei, E, i4, is32, d, valid);
#pragma unroll
    for (int j = 0; j < 4; j++)
        if ((unsigned)d[j] < (unsigned)N) atomicAdd(&deg[d[j]], 1);
}

// smem-staged coalesced exclusive scan (one block, n <= ~51k)
__global__ void scan_kernel(const int* __restrict__ deg, int* __restrict__ off,
                            int* __restrict__ cur, int n) {
    extern __shared__ int sd[];              // [n], staged deg -> becomes off
    __shared__ int part[1024];
    const int t = threadIdx.x;

    for (int i = t; i < n; i += 1024) sd[i] = deg[i];
    __syncthreads();

    const int chunk = (n + 1023) / 1024;
    int begin = t * chunk; if (begin > n) begin = n;
    int end = begin + chunk; if (end > n) end = n;

    int s = 0;
    for (int i = begin; i < end; i++) s += sd[i];
    part[t] = s;
    __syncthreads();

    for (int d = 1; d < 1024; d <<= 1) {
        int v = (t >= d) ? part[t - d] : 0;
        __syncthreads();
        part[t] += v;
        __syncthreads();
    }
    int run = (t == 0) ? 0 : part[t - 1];

    for (int i = begin; i < end; i++) { int tmp = sd[i]; sd[i] = run; run += tmp; }
    __syncthreads();

    for (int i = t; i < n; i += 1024) { int v = sd[i]; off[i] = v; cur[i] = v; }
    if (t == 1023) off[n] = part[1023];
}

__global__ void scatter_kernel(const void* __restrict__ ei, int E, int N,
                               int* __restrict__ cur, int* __restrict__ csr) {
    int is32 = detect_is32(ei, N);
    int i4 = (blockIdx.x * blockDim.x + threadIdx.x) * 4;
    if (i4 >= E) return;
    int valid = E - i4; if (valid > 4) valid = 4;
    int s[4], d[4];
    load_src4(ei, i4, is32, s, valid);
    load_dst4(ei, E, i4, is32, d, valid);
#pragma unroll
    for (int j = 0; j < 4; j++) {
        if ((unsigned)d[j] >= (unsigned)N || (unsigned)s[j] >= (unsigned)N) continue;
        int pos = atomicAdd(&cur[d[j]], 1);
        if ((unsigned)pos < (unsigned)EE) csr[pos] = s[j];
    }
}

// ---------------- mma.sync helpers ----------------
__device__ __forceinline__ uint32_t smem_u32(const void* p) {
    uint32_t a;
    asm("{ .reg .u64 t; cvta.to.shared.u64 t, %1; cvt.u32.u64 %0, t; }" : "=r"(a) : "l"(p));
    return a;
}
#define LDSM_X4(r0, r1, r2, r3, addr)                                          \
    asm volatile("ldmatrix.sync.aligned.m8n8.x4.shared.b16 {%0,%1,%2,%3}, [%4];" \
                 : "=r"(r0), "=r"(r1), "=r"(r2), "=r"(r3) : "r"(addr))
#define MMA16816(d, a, b)                                                      \
    asm volatile("mma.sync.aligned.m16n8k16.row.col.f32.bf16.bf16.f32 "        \
                 "{%0,%1,%2,%3}, {%4,%5,%6,%7}, {%8,%9}, {%0,%1,%2,%3};"       \
                 : "+f"((d)[0]), "+f"((d)[1]), "+f"((d)[2]), "+f"((d)[3])       \
                 : "r"((a)[0]), "r"((a)[1]), "r"((a)[2]), "r"((a)[3]),          \
                   "r"((b)[0]), "r"((b)[1]))

// ---------------- dual GEMM: out_p = A@W0 (fp16), out_q = A@W1 (fp32) --------
// 3-pass bf16 split: D = Ah*Bh + Ah*Bl + Al*Bh  (fp32 accum).
template <int NCOL>
__global__ void __launch_bounds__(512, 1)
mma_gemm(const float* __restrict__ A, const __nv_bfloat16* __restrict__ Bimg,
         __half* __restrict__ out_p, float* __restrict__ out_q, int M) {
    constexpr int NT   = 2 * NCOL;
    constexpr int LDK  = 136;
    constexpr int A_H  = 0;
    constexpr int A_L  = 128 * LDK;
    constexpr int B_H  = 2 * 128 * LDK;
    constexpr int B_L  = B_H + NT * LDK;
    constexpr int WC   = NT / 4;
    constexpr int NTL  = WC / 8;

    extern __shared__ __nv_bfloat16 sm[];
    const uint32_t sbase = smem_u32(sm);
    const int tid  = threadIdx.x;
    const int wid  = tid >> 5, lane = tid & 31;
    const int brow = blockIdx.x * 128;

    for (int i = tid; i < 128 * 32; i += 512) {
        int row = i >> 5, c4 = (i & 31) << 2;
        float4 v = make_float4(0.f, 0.f, 0.f, 0.f);
        if (brow + row < M)
            v = *(const float4*)(A + (size_t)(brow + row) * 128 + c4);
        __nv_bfloat16 h0, l0, h1, l1, h2, l2, h3, l3;
        split_bf16(v.x, h0, l0); split_bf16(v.y, h1, l1);
        split_bf16(v.z, h2, l2); split_bf16(v.w, h3, l3);
        int o = row * LDK + c4;
        *(__nv_bfloat162*)(sm + A_H + o)     = __nv_bfloat162(h0, h1);
        *(__nv_bfloat162*)(sm + A_H + o + 2) = __nv_bfloat162(h2, h3);
        *(__nv_bfloat162*)(sm + A_L + o)     = __nv_bfloat162(l0, l1);
        *(__nv_bfloat162*)(sm + A_L + o + 2) = __nv_bfloat162(l2, l3);
    }
    {
        const uint4* s = (const uint4*)Bimg;
        uint4* d = (uint4*)(sm + B_H);
        for (int i = tid; i < 2 * NT * LDK / 8; i += 512) d[i] = s[i];
    }
    __syncthreads();

    const int r0 = (wid >> 2) * 32;
    const int c0 = (wid & 3) * WC;
    const uint32_t frag_off = (uint32_t)((lane & 15) * LDK + (lane >> 4) * 8) * 2;

    float acc[2][NTL][4];
#pragma unroll
    for (int mt = 0; mt < 2; mt++)
#pragma unroll
        for (int nt = 0; nt < NTL; nt++)
#pragma unroll
            for (int j = 0; j < 4; j++) acc[mt][nt][j] = 0.f;

    const int APASS[3] = {A_H, A_H, A_L};
    const int BPASS[3] = {B_H, B_L, B_H};
#pragma unroll
    for (int pass = 0; pass < 3; pass++) {
        const uint32_t abase = sbase + (uint32_t)APASS[pass] * 2 + frag_off;
        const uint32_t bbase = sbase + (uint32_t)BPASS[pass] * 2 + frag_off;
#pragma unroll
        for (int ks = 0; ks < 8; ks++) {
            uint32_t a[2][4];
#pragma unroll
            for (int mt = 0; mt < 2; mt++)
                LDSM_X4(a[mt][0], a[mt][1], a[mt][2], a[mt][3],
                        abase + (uint32_t)((r0 + mt * 16) * LDK + ks * 16) * 2);
            uint32_t b[NTL][2];
#pragma unroll
            for (int np = 0; np < NTL / 2; np++) {
                uint32_t q0, q1, q2, q3;
                LDSM_X4(q0, q1, q2, q3,
                        bbase + (uint32_t)((c0 + np * 16) * LDK + ks * 16) * 2);
                b[2 * np][0] = q0; b[2 * np][1] = q2;
                b[2 * np + 1][0] = q1; b[2 * np + 1][1] = q3;
            }
#pragma unroll
            for (int mt = 0; mt < 2; mt++)
#pragma unroll
                for (int nt = 0; nt < NTL; nt++)
                    MMA16816(acc[mt][nt], a[mt], b[nt]);
        }
    }

    if (c0 < NCOL) {
#pragma unroll
        for (int mt = 0; mt < 2; mt++) {
            int rlo = brow + r0 + mt * 16 + (lane >> 2);
            int rhi = rlo + 8;
#pragma unroll
            for (int nt = 0; nt < NTL; nt++) {
                int col = c0 + nt * 8 + (lane & 3) * 2;
                if (rlo < M)
                    *(__half2*)(out_p + (size_t)rlo * NCOL + col) =
                        __floats2half2_rn(acc[mt][nt][0], acc[mt][nt][1]);
                if (rhi < M)
                    *(__half2*)(out_p + (size_t)rhi * NCOL + col) =
                        __floats2half2_rn(acc[mt][nt][2], acc[mt][nt][3]);
            }
        }
    } else {
        const int ncoff = c0 - NCOL;
#pragma unroll
        for (int mt = 0; mt < 2; mt++) {
            int rlo = brow + r0 + mt * 16 + (lane >> 2);
            int rhi = rlo + 8;
#pragma unroll
            for (int nt = 0; nt < NTL; nt++) {
                int col = ncoff + nt * 8 + (lane & 3) * 2;
                if (rlo < M)
                    *(float2*)(out_q + (size_t)rlo * NCOL + col) =
                        make_float2(acc[mt][nt][0], acc[mt][nt][1]);
                if (rhi < M)
                    *(float2*)(out_q + (size_t)rhi * NCOL + col) =
                        make_float2(acc[mt][nt][2], acc[mt][nt][3]);
            }
        }
    }
}

// ---------------- aggregation: fp16 gathers, fp32 accumulate ----------------
__device__ __forceinline__ float4 ld_half4(const __half* ptr) {
    uint2 u = *(const uint2*)ptr;
    float2 f0 = __half22float2(*reinterpret_cast<const __half2*>(&u.x));
    float2 f1 = __half22float2(*reinterpret_cast<const __half2*>(&u.y));
    return make_float4(f0.x, f0.y, f1.x, f1.y);
}

template <int D, bool RELU>
__global__ void agg_kernel(const __half* __restrict__ p, const float* __restrict__ q,
                           const float* __restrict__ bias,
                           const int* __restrict__ off, const int* __restrict__ csr,
                           float* __restrict__ out, int n) {
    const int tx = threadIdx.x;             // [0, D/4)
    const int v = blockIdx.x * blockDim.y + threadIdx.y;
    if (v >= n) return;
    const int s = off[v], e = off[v + 1];

    float4 a0 = make_float4(0.f, 0.f, 0.f, 0.f);
    float4 a1 = make_float4(0.f, 0.f, 0.f, 0.f);
    float4 a2 = make_float4(0.f, 0.f, 0.f, 0.f);
    float4 a3 = make_float4(0.f, 0.f, 0.f, 0.f);
    int i = s;
    for (; i + 4 <= e; i += 4) {
        int u0 = __ldg(&csr[i]),     u1 = __ldg(&csr[i + 1]);
        int u2 = __ldg(&csr[i + 2]), u3 = __ldg(&csr[i + 3]);
        float4 x0 = ld_half4(p + (size_t)u0 * D + tx * 4);
        float4 x1 = ld_half4(p + (size_t)u1 * D + tx * 4);
        float4 x2 = ld_half4(p + (size_t)u2 * D + tx * 4);
        float4 x3 = ld_half4(p + (size_t)u3 * D + tx * 4);
        a0.x += x0.x; a0.y += x0.y; a0.z += x0.z; a0.w += x0.w;
        a1.x += x1.x; a1.y += x1.y; a1.z += x1.z; a1.w += x1.w;
        a2.x += x2.x; a2.y += x2.y; a2.z += x2.z; a2.w += x2.w;
        a3.x += x3.x; a3.y += x3.y; a3.z += x3.z; a3.w += x3.w;
    }
    for (; i < e; i++) {
        int u0 = __ldg(&csr[i]);
        float4 x0 = ld_half4(p + (size_t)u0 * D + tx * 4);
        a0.x += x0.x; a0.y += x0.y; a0.z += x0.z; a0.w += x0.w;
    }
    a0.x += a1.x + a2.x + a3.x;
    a0.y += a1.y + a2.y + a3.y;
    a0.z += a1.z + a2.z + a3.z;
    a0.w += a1.w + a2.w + a3.w;

    const float inv = (e > s) ? 1.f / (float)(e - s) : 0.f;
    float4 bb = *(const float4*)(bias + tx * 4);
    float4 qq = *(const float4*)(q + (size_t)v * D + tx * 4);
    float4 r;
    r.x = a0.x * inv + bb.x + qq.x;
    r.y = a0.y * inv + bb.y + qq.y;
    r.z = a0.z * inv + bb.z + qq.z;
    r.w = a0.w * inv + bb.w + qq.w;
    if (RELU) {
        r.x = fmaxf(r.x, 0.f); r.y = fmaxf(r.y, 0.f);
        r.z = fmaxf(r.z, 0.f); r.w = fmaxf(r.w, 0.f);
    }
    *(float4*)(out + (size_t)v * D + tx * 4) = r;
}

// ---------------- launch ----------------
extern "C" void kernel_launch(void* const* d_in, const int* in_sizes, int n_in,
                              void* d_out, int out_size) {
    const float* x    = (const float*)d_in[0];
    const void*  ei   = d_in[1];
    const float* w1_l = (const float*)d_in[2];
    const float* b1   = (const float*)d_in[3];
    const float* w1_r = (const float*)d_in[4];
    const float* w2_l = (const float*)d_in[5];
    const float* b2   = (const float*)d_in[6];
    const float* w2_r = (const float*)d_in[7];
    float*       out  = (float*)d_out;

    const int E = in_sizes[1] / 2;
    const int N = in_sizes[0] / 128;

    static cudaStream_t s_side = nullptr;
    static cudaEvent_t ev_fork = nullptr, ev_csr = nullptr;
    if (!s_side) {
        cudaStreamCreateWithFlags(&s_side, cudaStreamNonBlocking);
        cudaEventCreateWithFlags(&ev_fork, cudaEventDisableTiming);
        cudaEventCreateWithFlags(&ev_csr,  cudaEventDisableTiming);
    }

    int *deg, *off, *cur, *csr;
    __half *p1, *p2;
    float *q1, *h, *q2;
    __nv_bfloat16 *img1, *img2;
    cudaGetSymbolAddress((void**)&deg, g_deg);
    cudaGetSymbolAddress((void**)&off, g_off);
    cudaGetSymbolAddress((void**)&cur, g_cur);
    cudaGetSymbolAddress((void**)&csr, g_csr);
    cudaGetSymbolAddress((void**)&p1, g_p1);
    cudaGetSymbolAddress((void**)&q1, g_q1);
    cudaGetSymbolAddress((void**)&h,  g_h);
    cudaGetSymbolAddress((void**)&p2, g_p2);
    cudaGetSymbolAddress((void**)&q2, g_q2);
    cudaGetSymbolAddress((void**)&img1, g_img1);
    cudaGetSymbolAddress((void**)&img2, g_img2);

    const int smem1 = (2 * 128 * 136 + 2 * 256 * 136) * 2;  // 208896
    const int smem2 = (2 * 128 * 136 + 2 * 128 * 136) * 2;  // 139264
    const int smemScan = (N + 1) * 4;                        // 200004 for N=50000
    cudaFuncSetAttribute((const void*)mma_gemm<128>,
                         cudaFuncAttributeMaxDynamicSharedMemorySize, smem1);
    cudaFuncSetAttribute((const void*)mma_gemm<64>,
                         cudaFuncAttributeMaxDynamicSharedMemorySize, smem2);
    cudaFuncSetAttribute((const void*)scan_kernel,
                         cudaFuncAttributeMaxDynamicSharedMemorySize, smemScan);

    const int tiles = (N + 127) / 128;
    const int eblocks = (E / 4 + 255) / 256 + 1;

    // ---- node 1: setup (zero deg + prep W) on main ----
    setup_kernel<<<(N + 255) / 256, 256>>>(w1_l, w1_r, w2_l, w2_r, img1, img2, deg, N);

    // ---- fork: CSR chain on side stream ----
    cudaEventRecord(ev_fork, 0);
    cudaStreamWaitEvent(s_side, ev_fork, 0);
    hist_kernel<<<eblocks, 256, 0, s_side>>>(ei, E, N, deg);
    scan_kernel<<<1, 1024, smemScan, s_side>>>(deg, off, cur, N);
    scatter_kernel<<<eblocks, 256, 0, s_side>>>(ei, E, N, cur, csr);
    cudaEventRecord(ev_csr, s_side);

    // ---- layer 1 GEMM on main (overlaps CSR chain) ----
    mma_gemm<128><<<tiles, 512, smem1>>>(x, img1, p1, q1, N);

    // ---- join ----
    cudaStreamWaitEvent(0, ev_csr, 0);

    // ---- agg1, gemm2, agg2 ----
    {
        dim3 blk(32, 8);
        agg_kernel<128, true><<<(N + 7) / 8, blk>>>(p1, q1, b1, off, csr, h, N);
    }
    mma_gemm<64><<<tiles, 512, smem2>>>(h, img2, p2, q2, N);
    {
        dim3 blk(16, 16);
        agg_kernel<64, false><<<(N + 15) / 16, blk>>>(p2, q2, b2, off, csr, out, N);
    }
}

// round 16
// speedup vs baseline: 1.5694x; 1.5694x over previous
#include <cuda_runtime.h>
#include <cuda_fp16.h>
#include <cstdint>

#define NN 50000
#define EE 600000

// ---------------- scratch ----------------
__device__ int    g_deg[NN];
__device__ int    g_off[NN + 1];
__device__ int    g_cur[NN];
__device__ int    g_csr[EE];
__device__ __half g_p1[(size_t)NN * 128];   // gathered -> fp16
__device__ float  g_q1[(size_t)NN * 128];
__device__ float  g_h [(size_t)NN * 128];
__device__ __half g_p2[(size_t)NN * 64];    // gathered -> fp16
__device__ float  g_q2[(size_t)NN * 64];
// prepped fp16 W images in GEMM smem layout [n][LDK=136]
__device__ __align__(16) __half g_img1[256 * 136];
__device__ __align__(16) __half g_img2[128 * 136];

// ---------------- inline dtype detection ----------------
__device__ __forceinline__ int detect_is32(const void* ei, int N) {
    const long long* p = (const long long*)ei;
    int lane = threadIdx.x & 31;
    bool bad = false;
#pragma unroll
    for (int j = 0; j < 2; j++) {
        long long v = p[lane * 2 + j];
        bad |= (v < 0 || v >= (long long)N);
    }
    return __any_sync(0xFFFFFFFF, bad);
}
__device__ __forceinline__ int load_idx(const void* ei, int pos, int is32) {
    if (is32) return ((const int*)ei)[pos];
    return (int)((const long long*)ei)[pos];
}

// ---------------- setup: zero deg + prep fp16 W images (fused) ----------------
__global__ void setup_kernel(const float* __restrict__ w1l, const float* __restrict__ w1r,
                             const float* __restrict__ w2l, const float* __restrict__ w2r,
                             __half* __restrict__ img1, __half* __restrict__ img2,
                             int* __restrict__ deg, int N) {
    int i = blockIdx.x * blockDim.x + threadIdx.x;
    if (i < N) deg[i] = 0;
    if (i < 32768) {                         // layer 1: NT=256
        int n = i >> 7, k = i & 127;
        float v = (n < 128) ? w1l[k * 128 + n] : w1r[k * 128 + (n - 128)];
        img1[n * 136 + k] = __float2half_rn(v);
    } else if (i < 49152) {                  // layer 2: NT=128
        int j = i - 32768;
        int n = j >> 7, k = j & 127;
        float v = (n < 64) ? w2l[k * 64 + n] : w2r[k * 64 + (n - 64)];
        img2[n * 136 + k] = __float2half_rn(v);
    }
}

// ---------------- CSR build (scalar, R14-proven) ----------------
__global__ void hist_kernel(const void* __restrict__ ei, int E, int N,
                            int* __restrict__ deg) {
    int is32 = detect_is32(ei, N);
    int i = blockIdx.x * blockDim.x + threadIdx.x;
    if (i >= E) return;
    int d = load_idx(ei, E + i, is32);
    if ((unsigned)d < (unsigned)N) atomicAdd(&deg[d], 1);
}

// smem-staged coalesced exclusive scan (one block, n <= ~51k)
__global__ void scan_kernel(const int* __restrict__ deg, int* __restrict__ off,
                            int* __restrict__ cur, int n) {
    extern __shared__ int sd[];
    __shared__ int part[1024];
    const int t = threadIdx.x;

    for (int i = t; i < n; i += 1024) sd[i] = deg[i];
    __syncthreads();

    const int chunk = (n + 1023) / 1024;
    int begin = t * chunk; if (begin > n) begin = n;
    int end = begin + chunk; if (end > n) end = n;

    int s = 0;
    for (int i = begin; i < end; i++) s += sd[i];
    part[t] = s;
    __syncthreads();

    for (int d = 1; d < 1024; d <<= 1) {
        int v = (t >= d) ? part[t - d] : 0;
        __syncthreads();
        part[t] += v;
        __syncthreads();
    }
    int run = (t == 0) ? 0 : part[t - 1];

    for (int i = begin; i < end; i++) { int tmp = sd[i]; sd[i] = run; run += tmp; }
    __syncthreads();

    for (int i = t; i < n; i += 1024) { int v = sd[i]; off[i] = v; cur[i] = v; }
    if (t == 1023) off[n] = part[1023];
}

__global__ void scatter_kernel(const void* __restrict__ ei, int E, int N,
                               int* __restrict__ cur, int* __restrict__ csr) {
    int is32 = detect_is32(ei, N);
    int i = blockIdx.x * blockDim.x + threadIdx.x;
    if (i >= E) return;
    int s = load_idx(ei, i, is32);
    int d = load_idx(ei, E + i, is32);
    if ((unsigned)d >= (unsigned)N || (unsigned)s >= (unsigned)N) return;
    int pos = atomicAdd(&cur[d], 1);
    if ((unsigned)pos < (unsigned)EE) csr[pos] = s;
}

// ---------------- mma.sync helpers ----------------
__device__ __forceinline__ uint32_t smem_u32(const void* p) {
    uint32_t a;
    asm("{ .reg .u64 t; cvta.to.shared.u64 t, %1; cvt.u32.u64 %0, t; }" : "=r"(a) : "l"(p));
    return a;
}
#define LDSM_X4(r0, r1, r2, r3, addr)                                          \
    asm volatile("ldmatrix.sync.aligned.m8n8.x4.shared.b16 {%0,%1,%2,%3}, [%4];" \
                 : "=r"(r0), "=r"(r1), "=r"(r2), "=r"(r3) : "r"(addr))
#define MMA16816H(d, a, b)                                                     \
    asm volatile("mma.sync.aligned.m16n8k16.row.col.f32.f16.f16.f32 "          \
                 "{%0,%1,%2,%3}, {%4,%5,%6,%7}, {%8,%9}, {%0,%1,%2,%3};"       \
                 : "+f"((d)[0]), "+f"((d)[1]), "+f"((d)[2]), "+f"((d)[3])       \
                 : "r"((a)[0]), "r"((a)[1]), "r"((a)[2]), "r"((a)[3]),          \
                   "r"((b)[0]), "r"((b)[1]))

// ---------------- dual GEMM: out_p = A@W0 (fp16), out_q = A@W1 (fp32) --------
// Single-pass fp16 (11-bit mantissa; R10-measured rel_err 3.9e-4).
// R14 shape: 512 threads, BM=128, 4x4 warp grid over concatenated NT=2*NCOL.
template <int NCOL>
__global__ void __launch_bounds__(512, 1)
mma_gemm(const float* __restrict__ A, const __half* __restrict__ Bimg,
         __half* __restrict__ out_p, float* __restrict__ out_q, int M) {
    constexpr int NT   = 2 * NCOL;
    constexpr int LDK  = 136;
    constexpr int B_OFF = 128 * LDK;         // A occupies [0, 128*LDK)
    constexpr int WC   = NT / 4;
    constexpr int NTL  = WC / 8;

    extern __shared__ __half sm[];
    const uint32_t sbase = smem_u32(sm);
    const int tid  = threadIdx.x;
    const int wid  = tid >> 5, lane = tid & 31;
    const int brow = blockIdx.x * 128;

    // A tile: fp32 -> fp16 smem
    for (int i = tid; i < 128 * 32; i += 512) {
        int row = i >> 5, c4 = (i & 31) << 2;
        float4 v = make_float4(0.f, 0.f, 0.f, 0.f);
        if (brow + row < M)
            v = *(const float4*)(A + (size_t)(brow + row) * 128 + c4);
        *(__half2*)(sm + row * LDK + c4)     = __floats2half2_rn(v.x, v.y);
        *(__half2*)(sm + row * LDK + c4 + 2) = __floats2half2_rn(v.z, v.w);
    }
    // B: straight copy of prepped fp16 image
    {
        const uint4* s = (const uint4*)Bimg;
        uint4* d = (uint4*)(sm + B_OFF);
        for (int i = tid; i < NT * LDK / 8; i += 512) d[i] = s[i];
    }
    __syncthreads();

    const int r0 = (wid >> 2) * 32;
    const int c0 = (wid & 3) * WC;
    const uint32_t frag_off = (uint32_t)((lane & 15) * LDK + (lane >> 4) * 8) * 2;
    const uint32_t abase = sbase + frag_off;
    const uint32_t bbase = sbase + (uint32_t)B_OFF * 2 + frag_off;

    float acc[2][NTL][4];
#pragma unroll
    for (int mt = 0; mt < 2; mt++)
#pragma unroll
        for (int nt = 0; nt < NTL; nt++)
#pragma unroll
            for (int j = 0; j < 4; j++) acc[mt][nt][j] = 0.f;

#pragma unroll
    for (int ks = 0; ks < 8; ks++) {
        uint32_t a[2][4];
#pragma unroll
        for (int mt = 0; mt < 2; mt++)
            LDSM_X4(a[mt][0], a[mt][1], a[mt][2], a[mt][3],
                    abase + (uint32_t)((r0 + mt * 16) * LDK + ks * 16) * 2);
        uint32_t b[NTL][2];
#pragma unroll
        for (int np = 0; np < NTL / 2; np++) {
            uint32_t q0, q1, q2, q3;
            LDSM_X4(q0, q1, q2, q3,
                    bbase + (uint32_t)((c0 + np * 16) * LDK + ks * 16) * 2);
            b[2 * np][0] = q0; b[2 * np][1] = q2;
            b[2 * np + 1][0] = q1; b[2 * np + 1][1] = q3;
        }
#pragma unroll
        for (int mt = 0; mt < 2; mt++)
#pragma unroll
            for (int nt = 0; nt < NTL; nt++)
                MMA16816H(acc[mt][nt], a[mt], b[nt]);
    }

    if (c0 < NCOL) {
#pragma unroll
        for (int mt = 0; mt < 2; mt++) {
            int rlo = brow + r0 + mt * 16 + (lane >> 2);
            int rhi = rlo + 8;
#pragma unroll
            for (int nt = 0; nt < NTL; nt++) {
                int col = c0 + nt * 8 + (lane & 3) * 2;
                if (rlo < M)
                    *(__half2*)(out_p + (size_t)rlo * NCOL + col) =
                        __floats2half2_rn(acc[mt][nt][0], acc[mt][nt][1]);
                if (rhi < M)
                    *(__half2*)(out_p + (size_t)rhi * NCOL + col) =
                        __floats2half2_rn(acc[mt][nt][2], acc[mt][nt][3]);
            }
        }
    } else {
        const int ncoff = c0 - NCOL;
#pragma unroll
        for (int mt = 0; mt < 2; mt++) {
            int rlo = brow + r0 + mt * 16 + (lane >> 2);
            int rhi = rlo + 8;
#pragma unroll
            for (int nt = 0; nt < NTL; nt++) {
                int col = ncoff + nt * 8 + (lane & 3) * 2;
                if (rlo < M)
                    *(float2*)(out_q + (size_t)rlo * NCOL + col) =
                        make_float2(acc[mt][nt][0], acc[mt][nt][1]);
                if (rhi < M)
                    *(float2*)(out_q + (size_t)rhi * NCOL + col) =
                        make_float2(acc[mt][nt][2], acc[mt][nt][3]);
            }
        }
    }
}

// ---------------- aggregation: fp16 gathers, fp32 accumulate ----------------
__device__ __forceinline__ float4 ld_half4(const __half* ptr) {
    uint2 u = *(const uint2*)ptr;
    float2 f0 = __half22float2(*reinterpret_cast<const __half2*>(&u.x));
    float2 f1 = __half22float2(*reinterpret_cast<const __half2*>(&u.y));
    return make_float4(f0.x, f0.y, f1.x, f1.y);
}

template <int D, bool RELU>
__global__ void agg_kernel(const __half* __restrict__ p, const float* __restrict__ q,
                           const float* __restrict__ bias,
                           const int* __restrict__ off, const int* __restrict__ csr,
                           float* __restrict__ out, int n) {
    const int tx = threadIdx.x;             // [0, D/4)
    const int v = blockIdx.x * blockDim.y + threadIdx.y;
    if (v >= n) return;
    const int s = off[v], e = off[v + 1];

    float4 a0 = make_float4(0.f, 0.f, 0.f, 0.f);
    float4 a1 = make_float4(0.f, 0.f, 0.f, 0.f);
    float4 a2 = make_float4(0.f, 0.f, 0.f, 0.f);
    float4 a3 = make_float4(0.f, 0.f, 0.f, 0.f);
    int i = s;
    for (; i + 4 <= e; i += 4) {
        int u0 = __ldg(&csr[i]),     u1 = __ldg(&csr[i + 1]);
        int u2 = __ldg(&csr[i + 2]), u3 = __ldg(&csr[i + 3]);
        float4 x0 = ld_half4(p + (size_t)u0 * D + tx * 4);
        float4 x1 = ld_half4(p + (size_t)u1 * D + tx * 4);
        float4 x2 = ld_half4(p + (size_t)u2 * D + tx * 4);
        float4 x3 = ld_half4(p + (size_t)u3 * D + tx * 4);
        a0.x += x0.x; a0.y += x0.y; a0.z += x0.z; a0.w += x0.w;
        a1.x += x1.x; a1.y += x1.y; a1.z += x1.z; a1.w += x1.w;
        a2.x += x2.x; a2.y += x2.y; a2.z += x2.z; a2.w += x2.w;
        a3.x += x3.x; a3.y += x3.y; a3.z += x3.z; a3.w += x3.w;
    }
    for (; i < e; i++) {
        int u0 = __ldg(&csr[i]);
        float4 x0 = ld_half4(p + (size_t)u0 * D + tx * 4);
        a0.x += x0.x; a0.y += x0.y; a0.z += x0.z; a0.w += x0.w;
    }
    a0.x += a1.x + a2.x + a3.x;
    a0.y += a1.y + a2.y + a3.y;
    a0.z += a1.z + a2.z + a3.z;
    a0.w += a1.w + a2.w + a3.w;

    const float inv = (e > s) ? 1.f / (float)(e - s) : 0.f;
    float4 bb = *(const float4*)(bias + tx * 4);
    float4 qq = *(const float4*)(q + (size_t)v * D + tx * 4);
    float4 r;
    r.x = a0.x * inv + bb.x + qq.x;
    r.y = a0.y * inv + bb.y + qq.y;
    r.z = a0.z * inv + bb.z + qq.z;
    r.w = a0.w * inv + bb.w + qq.w;
    if (RELU) {
        r.x = fmaxf(r.x, 0.f); r.y = fmaxf(r.y, 0.f);
        r.z = fmaxf(r.z, 0.f); r.w = fmaxf(r.w, 0.f);
    }
    *(float4*)(out + (size_t)v * D + tx * 4) = r;
}

// ---------------- launch ----------------
extern "C" void kernel_launch(void* const* d_in, const int* in_sizes, int n_in,
                              void* d_out, int out_size) {
    const float* x    = (const float*)d_in[0];
    const void*  ei   = d_in[1];
    const float* w1_l = (const float*)d_in[2];
    const float* b1   = (const float*)d_in[3];
    const float* w1_r = (const float*)d_in[4];
    const float* w2_l = (const float*)d_in[5];
    const float* b2   = (const float*)d_in[6];
    const float* w2_r = (const float*)d_in[7];
    float*       out  = (float*)d_out;

    const int E = in_sizes[1] / 2;
    const int N = in_sizes[0] / 128;

    static cudaStream_t s_side = nullptr;
    static cudaEvent_t ev_fork = nullptr, ev_csr = nullptr;
    if (!s_side) {
        cudaStreamCreateWithFlags(&s_side, cudaStreamNonBlocking);
        cudaEventCreateWithFlags(&ev_fork, cudaEventDisableTiming);
        cudaEventCreateWithFlags(&ev_csr,  cudaEventDisableTiming);
    }

    int *deg, *off, *cur, *csr;
    __half *p1, *p2, *img1, *img2;
    float *q1, *h, *q2;
    cudaGetSymbolAddress((void**)&deg, g_deg);
    cudaGetSymbolAddress((void**)&off, g_off);
    cudaGetSymbolAddress((void**)&cur, g_cur);
    cudaGetSymbolAddress((void**)&csr, g_csr);
    cudaGetSymbolAddress((void**)&p1, g_p1);
    cudaGetSymbolAddress((void**)&q1, g_q1);
    cudaGetSymbolAddress((void**)&h,  g_h);
    cudaGetSymbolAddress((void**)&p2, g_p2);
    cudaGetSymbolAddress((void**)&q2, g_q2);
    cudaGetSymbolAddress((void**)&img1, g_img1);
    cudaGetSymbolAddress((void**)&img2, g_img2);

    const int smem1 = (128 + 256) * 136 * 2;  // 104448
    const int smem2 = (128 + 128) * 136 * 2;  // 69632
    const int smemScan = (N + 1) * 4;         // 200004 for N=50000
    cudaFuncSetAttribute((const void*)mma_gemm<128>,
                         cudaFuncAttributeMaxDynamicSharedMemorySize, smem1);
    cudaFuncSetAttribute((const void*)mma_gemm<64>,
                         cudaFuncAttributeMaxDynamicSharedMemorySize, smem2);
    cudaFuncSetAttribute((const void*)scan_kernel,
                         cudaFuncAttributeMaxDynamicSharedMemorySize, smemScan);

    const int tiles = (N + 127) / 128;

    // ---- node 1: setup (zero deg + prep W) on main ----
    setup_kernel<<<(N + 255) / 256, 256>>>(w1_l, w1_r, w2_l, w2_r, img1, img2, deg, N);

    // ---- fork: CSR chain on side stream ----
    cudaEventRecord(ev_fork, 0);
    cudaStreamWaitEvent(s_side, ev_fork, 0);
    hist_kernel<<<(E + 255) / 256, 256, 0, s_side>>>(ei, E, N, deg);
    scan_kernel<<<1, 1024, smemScan, s_side>>>(deg, off, cur, N);
    scatter_kernel<<<(E + 255) / 256, 256, 0, s_side>>>(ei, E, N, cur, csr);
    cudaEventRecord(ev_csr, s_side);

    // ---- layer 1 GEMM on main (overlaps CSR chain) ----
    mma_gemm<128><<<tiles, 512, smem1>>>(x, img1, p1, q1, N);

    // ---- join ----
    cudaStreamWaitEvent(0, ev_csr, 0);

    // ---- agg1, gemm2, agg2 ----
    {
        dim3 blk(32, 8);
        agg_kernel<128, true><<<(N + 7) / 8, blk>>>(p1, q1, b1, off, csr, h, N);
    }
    mma_gemm<64><<<tiles, 512, smem2>>>(h, img2, p2, q2, N);
    {
        dim3 blk(16, 16);
        agg_kernel<64, false><<<(N + 15) / 16, blk>>>(p2, q2, b2, off, csr, out, N);
    }
}

// round 17
// speedup vs baseline: 1.6521x; 1.0527x over previous
#include <cuda_runtime.h>
#include <cuda_fp16.h>
#include <cstdint>

#define NN 50000
#define EE 600000

// ---------------- scratch ----------------
__device__ int    g_deg[NN];
__device__ int    g_off[NN + 1];
__device__ int    g_cur[NN];
__device__ int    g_csr[EE];
__device__ __half g_p1[(size_t)NN * 128];
__device__ __half g_q1[(size_t)NN * 128];
__device__ __half g_h [(size_t)NN * 128];
__device__ __half g_p2[(size_t)NN * 64];
__device__ __half g_q2[(size_t)NN * 64];
// prepped fp16 W images in GEMM smem layout [n][LDK=136]
__device__ __align__(16) __half g_img1[256 * 136];
__device__ __align__(16) __half g_img2[128 * 136];

// ---------------- inline dtype detection ----------------
__device__ __forceinline__ int detect_is32(const void* ei, int N) {
    const long long* p = (const long long*)ei;
    int lane = threadIdx.x & 31;
    bool bad = false;
#pragma unroll
    for (int j = 0; j < 2; j++) {
        long long v = p[lane * 2 + j];
        bad |= (v < 0 || v >= (long long)N);
    }
    return __any_sync(0xFFFFFFFF, bad);
}
__device__ __forceinline__ int load_idx(const void* ei, int pos, int is32) {
    if (is32) return ((const int*)ei)[pos];
    return (int)((const long long*)ei)[pos];
}

// ---------------- setup: zero deg + prep fp16 W images (fused) ----------------
__global__ void setup_kernel(const float* __restrict__ w1l, const float* __restrict__ w1r,
                             const float* __restrict__ w2l, const float* __restrict__ w2r,
                             __half* __restrict__ img1, __half* __restrict__ img2,
                             int* __restrict__ deg, int N) {
    int i = blockIdx.x * blockDim.x + threadIdx.x;
    if (i < N) deg[i] = 0;
    if (i < 32768) {                         // layer 1: NT=256
        int n = i >> 7, k = i & 127;
        float v = (n < 128) ? w1l[k * 128 + n] : w1r[k * 128 + (n - 128)];
        img1[n * 136 + k] = __float2half_rn(v);
    } else if (i < 49152) {                  // layer 2: NT=128
        int j = i - 32768;
        int n = j >> 7, k = j & 127;
        float v = (n < 64) ? w2l[k * 64 + n] : w2r[k * 64 + (n - 64)];
        img2[n * 136 + k] = __float2half_rn(v);
    }
}

// ---------------- CSR build (scalar, R14-proven) ----------------
__global__ void hist_kernel(const void* __restrict__ ei, int E, int N,
                            int* __restrict__ deg) {
    int is32 = detect_is32(ei, N);
    int i = blockIdx.x * blockDim.x + threadIdx.x;
    if (i >= E) return;
    int d = load_idx(ei, E + i, is32);
    if ((unsigned)d < (unsigned)N) atomicAdd(&deg[d], 1);
}

// smem-staged coalesced exclusive scan (one block, n <= ~51k)
__global__ void scan_kernel(const int* __restrict__ deg, int* __restrict__ off,
                            int* __restrict__ cur, int n) {
    extern __shared__ int sd[];
    __shared__ int part[1024];
    const int t = threadIdx.x;

    for (int i = t; i < n; i += 1024) sd[i] = deg[i];
    __syncthreads();

    const int chunk = (n + 1023) / 1024;
    int begin = t * chunk; if (begin > n) begin = n;
    int end = begin + chunk; if (end > n) end = n;

    int s = 0;
    for (int i = begin; i < end; i++) s += sd[i];
    part[t] = s;
    __syncthreads();

    for (int d = 1; d < 1024; d <<= 1) {
        int v = (t >= d) ? part[t - d] : 0;
        __syncthreads();
        part[t] += v;
        __syncthreads();
    }
    int run = (t == 0) ? 0 : part[t - 1];

    for (int i = begin; i < end; i++) { int tmp = sd[i]; sd[i] = run; run += tmp; }
    __syncthreads();

    for (int i = t; i < n; i += 1024) { int v = sd[i]; off[i] = v; cur[i] = v; }
    if (t == 1023) off[n] = part[1023];
}

__global__ void scatter_kernel(const void* __restrict__ ei, int E, int N,
                               int* __restrict__ cur, int* __restrict__ csr) {
    int is32 = detect_is32(ei, N);
    int i = blockIdx.x * blockDim.x + threadIdx.x;
    if (i >= E) return;
    int s = load_idx(ei, i, is32);
    int d = load_idx(ei, E + i, is32);
    if ((unsigned)d >= (unsigned)N || (unsigned)s >= (unsigned)N) return;
    int pos = atomicAdd(&cur[d], 1);
    if ((unsigned)pos < (unsigned)EE) csr[pos] = s;
}

// ---------------- mma.sync helpers ----------------
__device__ __forceinline__ uint32_t smem_u32(const void* p) {
    uint32_t a;
    asm("{ .reg .u64 t; cvta.to.shared.u64 t, %1; cvt.u32.u64 %0, t; }" : "=r"(a) : "l"(p));
    return a;
}
#define LDSM_X4(r0, r1, r2, r3, addr)                                          \
    asm volatile("ldmatrix.sync.aligned.m8n8.x4.shared.b16 {%0,%1,%2,%3}, [%4];" \
                 : "=r"(r0), "=r"(r1), "=r"(r2), "=r"(r3) : "r"(addr))
#define MMA16816H(d, a, b)                                                     \
    asm volatile("mma.sync.aligned.m16n8k16.row.col.f32.f16.f16.f32 "          \
                 "{%0,%1,%2,%3}, {%4,%5,%6,%7}, {%8,%9}, {%0,%1,%2,%3};"       \
                 : "+f"((d)[0]), "+f"((d)[1]), "+f"((d)[2]), "+f"((d)[3])       \
                 : "r"((a)[0]), "r"((a)[1]), "r"((a)[2]), "r"((a)[3]),          \
                   "r"((b)[0]), "r"((b)[1]))

// ---------------- dual GEMM: out_p = A@W0, out_q = A@W1 (both fp16) ----------
// Single-pass fp16. R14 shape: 512 threads, BM=128, 4x4 warps over NT=2*NCOL.
template <int NCOL, bool A_HALF>
__global__ void __launch_bounds__(512, 1)
mma_gemm(const void* __restrict__ Araw, const __half* __restrict__ Bimg,
         __half* __restrict__ out_p, __half* __restrict__ out_q, int M) {
    constexpr int NT   = 2 * NCOL;
    constexpr int LDK  = 136;
    constexpr int B_OFF = 128 * LDK;
    constexpr int WC   = NT / 4;
    constexpr int NTL  = WC / 8;

    extern __shared__ __half sm[];
    const uint32_t sbase = smem_u32(sm);
    const int tid  = threadIdx.x;
    const int wid  = tid >> 5, lane = tid & 31;
    const int brow = blockIdx.x * 128;

    // ---- stage A ----
    if (A_HALF) {
        const __half* A = (const __half*)Araw;
        for (int i = tid; i < 128 * 16; i += 512) {      // 16 uint4 per row
            int row = i >> 4, c8 = (i & 15) << 3;
            uint4 v = make_uint4(0, 0, 0, 0);
            if (brow + row < M)
                v = *(const uint4*)(A + (size_t)(brow + row) * 128 + c8);
            *(uint4*)(sm + row * LDK + c8) = v;
        }
    } else {
        const float* A = (const float*)Araw;
        for (int i = tid; i < 128 * 32; i += 512) {
            int row = i >> 5, c4 = (i & 31) << 2;
            float4 v = make_float4(0.f, 0.f, 0.f, 0.f);
            if (brow + row < M)
                v = *(const float4*)(A + (size_t)(brow + row) * 128 + c4);
            *(__half2*)(sm + row * LDK + c4)     = __floats2half2_rn(v.x, v.y);
            *(__half2*)(sm + row * LDK + c4 + 2) = __floats2half2_rn(v.z, v.w);
        }
    }
    // ---- stage B (straight copy of prepped fp16 image) ----
    {
        const uint4* s = (const uint4*)Bimg;
        uint4* d = (uint4*)(sm + B_OFF);
        for (int i = tid; i < NT * LDK / 8; i += 512) d[i] = s[i];
    }
    __syncthreads();

    const int r0 = (wid >> 2) * 32;
    const int c0 = (wid & 3) * WC;
    const uint32_t frag_off = (uint32_t)((lane & 15) * LDK + (lane >> 4) * 8) * 2;
    const uint32_t abase = sbase + frag_off;
    const uint32_t bbase = sbase + (uint32_t)B_OFF * 2 + frag_off;

    float acc[2][NTL][4];
#pragma unroll
    for (int mt = 0; mt < 2; mt++)
#pragma unroll
        for (int nt = 0; nt < NTL; nt++)
#pragma unroll
            for (int j = 0; j < 4; j++) acc[mt][nt][j] = 0.f;

#pragma unroll
    for (int ks = 0; ks < 8; ks++) {
        uint32_t a[2][4];
#pragma unroll
        for (int mt = 0; mt < 2; mt++)
            LDSM_X4(a[mt][0], a[mt][1], a[mt][2], a[mt][3],
                    abase + (uint32_t)((r0 + mt * 16) * LDK + ks * 16) * 2);
        uint32_t b[NTL][2];
#pragma unroll
        for (int np = 0; np < NTL / 2; np++) {
            uint32_t q0, q1, q2, q3;
            LDSM_X4(q0, q1, q2, q3,
                    bbase + (uint32_t)((c0 + np * 16) * LDK + ks * 16) * 2);
            b[2 * np][0] = q0; b[2 * np][1] = q2;
            b[2 * np + 1][0] = q1; b[2 * np + 1][1] = q3;
        }
#pragma unroll
        for (int mt = 0; mt < 2; mt++)
#pragma unroll
            for (int nt = 0; nt < NTL; nt++)
                MMA16816H(acc[mt][nt], a[mt], b[nt]);
    }

    __half* dst = (c0 < NCOL) ? out_p : out_q;
    const int ncoff = (c0 < NCOL) ? c0 : (c0 - NCOL);
#pragma unroll
    for (int mt = 0; mt < 2; mt++) {
        int rlo = brow + r0 + mt * 16 + (lane >> 2);
        int rhi = rlo + 8;
#pragma unroll
        for (int nt = 0; nt < NTL; nt++) {
            int col = ncoff + nt * 8 + (lane & 3) * 2;
            if (rlo < M)
                *(__half2*)(dst + (size_t)rlo * NCOL + col) =
                    __floats2half2_rn(acc[mt][nt][0], acc[mt][nt][1]);
            if (rhi < M)
                *(__half2*)(dst + (size_t)rhi * NCOL + col) =
                    __floats2half2_rn(acc[mt][nt][2], acc[mt][nt][3]);
        }
    }
}

// ---------------- aggregation: fp16 gathers + fp16 q, fp32 accumulate --------
__device__ __forceinline__ float4 ld_half4(const __half* ptr) {
    uint2 u = *(const uint2*)ptr;
    float2 f0 = __half22float2(*reinterpret_cast<const __half2*>(&u.x));
    float2 f1 = __half22float2(*reinterpret_cast<const __half2*>(&u.y));
    return make_float4(f0.x, f0.y, f1.x, f1.y);
}

// OUT_HALF: true -> write fp16 (h), false -> write fp32 (final out)
template <int D, bool RELU, bool OUT_HALF>
__global__ void agg_kernel(const __half* __restrict__ p, const __half* __restrict__ q,
                           const float* __restrict__ bias,
                           const int* __restrict__ off, const int* __restrict__ csr,
                           void* __restrict__ outraw, int n) {
    const int tx = threadIdx.x;             // [0, D/4)
    const int v = blockIdx.x * blockDim.y + threadIdx.y;
    if (v >= n) return;
    const int s = off[v], e = off[v + 1];

    float4 a0 = make_float4(0.f, 0.f, 0.f, 0.f);
    float4 a1 = make_float4(0.f, 0.f, 0.f, 0.f);
    float4 a2 = make_float4(0.f, 0.f, 0.f, 0.f);
    float4 a3 = make_float4(0.f, 0.f, 0.f, 0.f);
    int i = s;
    for (; i + 4 <= e; i += 4) {
        int u0 = __ldg(&csr[i]),     u1 = __ldg(&csr[i + 1]);
        int u2 = __ldg(&csr[i + 2]), u3 = __ldg(&csr[i + 3]);
        float4 x0 = ld_half4(p + (size_t)u0 * D + tx * 4);
        float4 x1 = ld_half4(p + (size_t)u1 * D + tx * 4);
        float4 x2 = ld_half4(p + (size_t)u2 * D + tx * 4);
        float4 x3 = ld_half4(p + (size_t)u3 * D + tx * 4);
        a0.x += x0.x; a0.y += x0.y; a0.z += x0.z; a0.w += x0.w;
        a1.x += x1.x; a1.y += x1.y; a1.z += x1.z; a1.w += x1.w;
        a2.x += x2.x; a2.y += x2.y; a2.z += x2.z; a2.w += x2.w;
        a3.x += x3.x; a3.y += x3.y; a3.z += x3.z; a3.w += x3.w;
    }
    for (; i < e; i++) {
        int u0 = __ldg(&csr[i]);
        float4 x0 = ld_half4(p + (size_t)u0 * D + tx * 4);
        a0.x += x0.x; a0.y += x0.y; a0.z += x0.z; a0.w += x0.w;
    }
    a0.x += a1.x + a2.x + a3.x;
    a0.y += a1.y + a2.y + a3.y;
    a0.z += a1.z + a2.z + a3.z;
    a0.w += a1.w + a2.w + a3.w;

    const float inv = (e > s) ? 1.f / (float)(e - s) : 0.f;
    float4 bb = *(const float4*)(bias + tx * 4);
    float4 qq = ld_half4(q + (size_t)v * D + tx * 4);
    float rx = a0.x * inv + bb.x + qq.x;
    float ry = a0.y * inv + bb.y + qq.y;
    float rz = a0.z * inv + bb.z + qq.z;
    float rw = a0.w * inv + bb.w + qq.w;
    if (RELU) {
        rx = fmaxf(rx, 0.f); ry = fmaxf(ry, 0.f);
        rz = fmaxf(rz, 0.f); rw = fmaxf(rw, 0.f);
    }
    if (OUT_HALF) {
        __half* out = (__half*)outraw;
        uint2 st;
        __half2 h01 = __floats2half2_rn(rx, ry);
        __half2 h23 = __floats2half2_rn(rz, rw);
        st.x = *reinterpret_cast<uint32_t*>(&h01);
        st.y = *reinterpret_cast<uint32_t*>(&h23);
        *(uint2*)(out + (size_t)v * D + tx * 4) = st;
    } else {
        float* out = (float*)outraw;
        *(float4*)(out + (size_t)v * D + tx * 4) = make_float4(rx, ry, rz, rw);
    }
}

// ---------------- launch ----------------
extern "C" void kernel_launch(void* const* d_in, const int* in_sizes, int n_in,
                              void* d_out, int out_size) {
    const float* x    = (const float*)d_in[0];
    const void*  ei   = d_in[1];
    const float* w1_l = (const float*)d_in[2];
    const float* b1   = (const float*)d_in[3];
    const float* w1_r = (const float*)d_in[4];
    const float* w2_l = (const float*)d_in[5];
    const float* b2   = (const float*)d_in[6];
    const float* w2_r = (const float*)d_in[7];
    float*       out  = (float*)d_out;

    const int E = in_sizes[1] / 2;
    const int N = in_sizes[0] / 128;

    static cudaStream_t s_side = nullptr;
    static cudaEvent_t ev_fork = nullptr, ev_csr = nullptr;
    if (!s_side) {
        cudaStreamCreateWithFlags(&s_side, cudaStreamNonBlocking);
        cudaEventCreateWithFlags(&ev_fork, cudaEventDisableTiming);
        cudaEventCreateWithFlags(&ev_csr,  cudaEventDisableTiming);
    }

    int *deg, *off, *cur, *csr;
    __half *p1, *q1, *h, *p2, *q2, *img1, *img2;
    cudaGetSymbolAddress((void**)&deg, g_deg);
    cudaGetSymbolAddress((void**)&off, g_off);
    cudaGetSymbolAddress((void**)&cur, g_cur);
    cudaGetSymbolAddress((void**)&csr, g_csr);
    cudaGetSymbolAddress((void**)&p1, g_p1);
    cudaGetSymbolAddress((void**)&q1, g_q1);
    cudaGetSymbolAddress((void**)&h,  g_h);
    cudaGetSymbolAddress((void**)&p2, g_p2);
    cudaGetSymbolAddress((void**)&q2, g_q2);
    cudaGetSymbolAddress((void**)&img1, g_img1);
    cudaGetSymbolAddress((void**)&img2, g_img2);

    const int smem1 = (128 + 256) * 136 * 2;  // 104448
    const int smem2 = (128 + 128) * 136 * 2;  // 69632
    const int smemScan = (N + 1) * 4;
    cudaFuncSetAttribute((const void*)mma_gemm<128, false>,
                         cudaFuncAttributeMaxDynamicSharedMemorySize, smem1);
    cudaFuncSetAttribute((const void*)mma_gemm<64, true>,
                         cudaFuncAttributeMaxDynamicSharedMemorySize, smem2);
    cudaFuncSetAttribute((const void*)scan_kernel,
                         cudaFuncAttributeMaxDynamicSharedMemorySize, smemScan);

    const int tiles = (N + 127) / 128;

    // ---- node 1: setup (zero deg + prep W) on main ----
    setup_kernel<<<(N + 255) / 256, 256>>>(w1_l, w1_r, w2_l, w2_r, img1, img2, deg, N);

    // ---- fork: CSR chain on side stream ----
    cudaEventRecord(ev_fork, 0);
    cudaStreamWaitEvent(s_side, ev_fork, 0);
    hist_kernel<<<(E + 255) / 256, 256, 0, s_side>>>(ei, E, N, deg);
    scan_kernel<<<1, 1024, smemScan, s_side>>>(deg, off, cur, N);
    scatter_kernel<<<(E + 255) / 256, 256, 0, s_side>>>(ei, E, N, cur, csr);
    cudaEventRecord(ev_csr, s_side);

    // ---- layer 1 GEMM on main (overlaps CSR chain) ----
    mma_gemm<128, false><<<tiles, 512, smem1>>>(x, img1, p1, q1, N);

    // ---- join ----
    cudaStreamWaitEvent(0, ev_csr, 0);

    // ---- agg1 (-> h fp16), gemm2, agg2 (-> out fp32) ----
    {
        dim3 blk(32, 8);
        agg_kernel<128, true, true><<<(N + 7) / 8, blk>>>(p1, q1, b1, off, csr, h, N);
    }
    mma_gemm<64, true><<<tiles, 512, smem2>>>(h, img2, p2, q2, N);
    {
        dim3 blk(16, 16);
        agg_kernel<64, false, false><<<(N + 15) / 16, blk>>>(p2, q2, b2, off, csr, out, N);
    }
}